// round 8
// baseline (speedup 1.0000x reference)
#include <cuda_runtime.h>

// Problem constants
#define NB    32
#define NH    64
#define NW    64
#define NT    100
#define COUT  8
#define KS    6
#define LP    2

// Tiling
#define TILE_W 16
#define TILE_H 8
#define HALO_W (TILE_W + KS - 1)   // 21
#define HALO_H (TILE_H + KS - 1)   // 13
#define NPIX   (HALO_W * HALO_H)   // 273
#define NTHR   128                 // 16 x 8, one thread per pixel, ALL 8 couts per thread
#define NCH    13                  // chunks 0..11 are 8 timesteps, chunk 12 is 4 (t=96..99)
#define NHWT   (NH * NW * NT)      // 409600
#define PSTRIDE 5                  // u64 per pixel in smem (40B stride -> conflict-free LDS.64)
#define NBUF   3                   // triple buffer, prefetch distance 2, 1 sync per chunk

typedef unsigned long long u64;

__device__ __forceinline__ void upk2(u64 v, float& lo, float& hi) {
    asm("mov.b64 {%0, %1}, %2;" : "=f"(lo), "=f"(hi) : "l"(v));
}
__device__ __forceinline__ u64 fma2(u64 a, u64 b, u64 c) {
    u64 d; asm("fma.rn.f32x2 %0, %1, %2, %3;" : "=l"(d) : "l"(a), "l"(b), "l"(c)); return d;
}
__device__ __forceinline__ unsigned smem_u32(const void* p) {
    return (unsigned)__cvta_generic_to_shared(p);
}
// 8-byte cp.async: only needs 8B alignment (PSTRIDE=5 pixel bases are 8B aligned)
__device__ __forceinline__ void cp8(unsigned dst, const void* src) {
    asm volatile("cp.async.ca.shared.global [%0], [%1], 8;" :: "r"(dst), "l"(src));
}
__device__ __forceinline__ void cp_commit() { asm volatile("cp.async.commit_group;" ::: "memory"); }
__device__ __forceinline__ void cp_wait1()  { asm volatile("cp.async.wait_group 1;" ::: "memory"); }
__device__ __forceinline__ void cp_wait0()  { asm volatile("cp.async.wait_group 0;" ::: "memory"); }

// exact reference recurrence step: ut = (ut - st_prev*thr) + wx ; st = (ut > 0)
__device__ __forceinline__ float stepf(float& u, float wx, float thr) {
    u = (u - (u > 0.f ? thr : 0.f)) + wx;
    return (u > 0.f) ? 1.f : 0.f;
}

__global__ __launch_bounds__(NTHR, 4)   // 128 regs cap; 4 blocks/SM (16 warps)
void sconv_spike_kernel(const float* __restrict__ x,
                        const float* __restrict__ w,
                        const float* __restrict__ thr_p,
                        float* __restrict__ out)
{
    // triple-buffered input tile: pixel stride 5 u64 (40B) -> conflict-free LDS.64
    __shared__ u64 sx[NBUF][NPIX * PSTRIDE];
    // weights tap-major: sw2[tap*8 + cout], each duplicated (w,w) for f32x2
    __shared__ __align__(16) u64 sw2[KS * KS * COUT];

    const int tx  = threadIdx.x;
    const int ty  = threadIdx.y;
    const int tid = tx + TILE_W * ty;
    const int b   = blockIdx.z;
    const int h0  = blockIdx.y * TILE_H;
    const int w0  = blockIdx.x * TILE_W;

    // weights: transpose [cout][tap] -> [tap][cout], duplicate into both lanes
    for (int i = tid; i < KS * KS * COUT; i += NTHR) {
        int tap = i >> 3, c = i & 7;
        unsigned bits = __float_as_uint(w[c * (KS * KS) + tap]);
        sw2[i] = ((u64)bits << 32) | (u64)bits;
    }
    // zero OOB halo pixels in all buffers once (never written by cp8)
    for (int pix = tid; pix < NPIX; pix += NTHR) {
        int r = pix / HALO_W, c = pix % HALO_W;
        int gh = h0 - LP + r, gw = w0 - LP + c;
        if (gh < 0 || gh >= NH || gw < 0 || gw >= NW) {
#pragma unroll
            for (int bb = 0; bb < NBUF; bb++)
#pragma unroll
                for (int j = 0; j < 4; j++)
                    sx[bb][pix * PSTRIDE + j] = 0ull;
        }
    }
    const float thr = thr_p[0];

    const float* xb = x + (size_t)b * NH * NW * NT;
    const int h  = h0 + ty;
    const int wq = w0 + tx;
    float* obase = out + (size_t)b * COUT * NHWT
                       + ((size_t)h * NW + wq) * NT;

    float ut[COUT];
#pragma unroll
    for (int c = 0; c < COUT; c++) ut[c] = 0.f;

    // chunk loader: chunk k -> t0 = 8k; full chunks load 4 u64/pixel, tail loads 2
    auto load_chunk = [&](int k) {
        int buf = k % NBUF;
        int t0  = k * 8;
        int nu8 = (k == NCH - 1) ? 2 : 4;
        int total = NPIX * nu8;
        for (int idx = tid; idx < total; idx += NTHR) {
            int pix, j;
            if (nu8 == 4) { pix = idx >> 2; j = idx & 3; }
            else          { pix = idx >> 1; j = idx & 1; }
            int r = pix / HALO_W, c = pix % HALO_W;
            int gh = h0 - LP + r, gw = w0 - LP + c;
            if (gh >= 0 && gh < NH && gw >= 0 && gw < NW) {
                const float* src = xb + ((size_t)gh * NW + gw) * NT + t0 + j * 2;
                cp8(smem_u32(&sx[buf][pix * PSTRIDE + j]), src);
            }
        }
        cp_commit();
    };

    load_chunk(0);
    load_chunk(1);

#pragma unroll 1
    for (int i = 0; i < NCH; i++) {
        // outstanding cp.async groups at this point: {i, i+1}∩range
        if (i + 1 < NCH) cp_wait1();   // group i retired
        else             cp_wait0();
        __syncthreads();               // chunk i visible; iter i-1 reads done
        if (i + 2 < NCH) load_chunk(i + 2);   // safe: after the barrier

        const int buf = i % NBUF;
        const int t0  = i * 8;
        const bool full = (i != NCH - 1);

        // 8 couts x 4 timestep-pairs of f32x2 accumulators (full chunk)
        u64 a0[COUT], a1[COUT], a2[COUT], a3[COUT];
#pragma unroll
        for (int c = 0; c < COUT; c++) { a0[c] = 0; a1[c] = 0; a2[c] = 0; a3[c] = 0; }

        if (full) {
#pragma unroll
            for (int kh = 0; kh < KS; kh++) {
#pragma unroll
                for (int kw = 0; kw < KS; kw++) {
                    const int tap = kh * KS + kw;
                    const u64* xp = &sx[buf][((ty + kh) * HALO_W + (tx + kw)) * PSTRIDE];
                    u64 x0 = xp[0], x1 = xp[1], x2 = xp[2], x3 = xp[3];
                    // 8 cout weights via 4 broadcast LDS.128 (single address)
                    ulonglong2 w01 = *(const ulonglong2*)&sw2[tap * COUT + 0];
                    ulonglong2 w23 = *(const ulonglong2*)&sw2[tap * COUT + 2];
                    ulonglong2 w45 = *(const ulonglong2*)&sw2[tap * COUT + 4];
                    ulonglong2 w67 = *(const ulonglong2*)&sw2[tap * COUT + 6];
                    a0[0] = fma2(x0, w01.x, a0[0]); a1[0] = fma2(x1, w01.x, a1[0]);
                    a2[0] = fma2(x2, w01.x, a2[0]); a3[0] = fma2(x3, w01.x, a3[0]);
                    a0[1] = fma2(x0, w01.y, a0[1]); a1[1] = fma2(x1, w01.y, a1[1]);
                    a2[1] = fma2(x2, w01.y, a2[1]); a3[1] = fma2(x3, w01.y, a3[1]);
                    a0[2] = fma2(x0, w23.x, a0[2]); a1[2] = fma2(x1, w23.x, a1[2]);
                    a2[2] = fma2(x2, w23.x, a2[2]); a3[2] = fma2(x3, w23.x, a3[2]);
                    a0[3] = fma2(x0, w23.y, a0[3]); a1[3] = fma2(x1, w23.y, a1[3]);
                    a2[3] = fma2(x2, w23.y, a2[3]); a3[3] = fma2(x3, w23.y, a3[3]);
                    a0[4] = fma2(x0, w45.x, a0[4]); a1[4] = fma2(x1, w45.x, a1[4]);
                    a2[4] = fma2(x2, w45.x, a2[4]); a3[4] = fma2(x3, w45.x, a3[4]);
                    a0[5] = fma2(x0, w45.y, a0[5]); a1[5] = fma2(x1, w45.y, a1[5]);
                    a2[5] = fma2(x2, w45.y, a2[5]); a3[5] = fma2(x3, w45.y, a3[5]);
                    a0[6] = fma2(x0, w67.x, a0[6]); a1[6] = fma2(x1, w67.x, a1[6]);
                    a2[6] = fma2(x2, w67.x, a2[6]); a3[6] = fma2(x3, w67.x, a3[6]);
                    a0[7] = fma2(x0, w67.y, a0[7]); a1[7] = fma2(x1, w67.y, a1[7]);
                    a2[7] = fma2(x2, w67.y, a2[7]); a3[7] = fma2(x3, w67.y, a3[7]);
                }
            }
#pragma unroll
            for (int c = 0; c < COUT; c++) {
                float wx0, wx1, wx2, wx3, wx4, wx5, wx6, wx7;
                upk2(a0[c], wx0, wx1); upk2(a1[c], wx2, wx3);
                upk2(a2[c], wx4, wx5); upk2(a3[c], wx6, wx7);
                float u = ut[c];
                float s0 = stepf(u, wx0, thr), s1 = stepf(u, wx1, thr);
                float s2 = stepf(u, wx2, thr), s3 = stepf(u, wx3, thr);
                float s4 = stepf(u, wx4, thr), s5 = stepf(u, wx5, thr);
                float s6 = stepf(u, wx6, thr), s7 = stepf(u, wx7, thr);
                ut[c] = u;
                float4* p = (float4*)(obase + (size_t)c * NHWT + t0);
                p[0] = make_float4(s0, s1, s2, s3);   // 32B contiguous -> full sectors
                p[1] = make_float4(s4, s5, s6, s7);
            }
        } else {
            // tail: t = 96..99
#pragma unroll
            for (int kh = 0; kh < KS; kh++) {
#pragma unroll
                for (int kw = 0; kw < KS; kw++) {
                    const int tap = kh * KS + kw;
                    const u64* xp = &sx[buf][((ty + kh) * HALO_W + (tx + kw)) * PSTRIDE];
                    u64 x0 = xp[0], x1 = xp[1];
                    ulonglong2 w01 = *(const ulonglong2*)&sw2[tap * COUT + 0];
                    ulonglong2 w23 = *(const ulonglong2*)&sw2[tap * COUT + 2];
                    ulonglong2 w45 = *(const ulonglong2*)&sw2[tap * COUT + 4];
                    ulonglong2 w67 = *(const ulonglong2*)&sw2[tap * COUT + 6];
                    a0[0] = fma2(x0, w01.x, a0[0]); a1[0] = fma2(x1, w01.x, a1[0]);
                    a0[1] = fma2(x0, w01.y, a0[1]); a1[1] = fma2(x1, w01.y, a1[1]);
                    a0[2] = fma2(x0, w23.x, a0[2]); a1[2] = fma2(x1, w23.x, a1[2]);
                    a0[3] = fma2(x0, w23.y, a0[3]); a1[3] = fma2(x1, w23.y, a1[3]);
                    a0[4] = fma2(x0, w45.x, a0[4]); a1[4] = fma2(x1, w45.x, a1[4]);
                    a0[5] = fma2(x0, w45.y, a0[5]); a1[5] = fma2(x1, w45.y, a1[5]);
                    a0[6] = fma2(x0, w67.x, a0[6]); a1[6] = fma2(x1, w67.x, a1[6]);
                    a0[7] = fma2(x0, w67.y, a0[7]); a1[7] = fma2(x1, w67.y, a1[7]);
                }
            }
#pragma unroll
            for (int c = 0; c < COUT; c++) {
                float wx0, wx1, wx2, wx3;
                upk2(a0[c], wx0, wx1); upk2(a1[c], wx2, wx3);
                float u = ut[c];
                float s0 = stepf(u, wx0, thr), s1 = stepf(u, wx1, thr);
                float s2 = stepf(u, wx2, thr), s3 = stepf(u, wx3, thr);
                ut[c] = u;
                *(float4*)(obase + (size_t)c * NHWT + t0) = make_float4(s0, s1, s2, s3);
            }
        }
    }
}

extern "C" void kernel_launch(void* const* d_in, const int* in_sizes, int n_in,
                              void* d_out, int out_size)
{
    const float* x   = (const float*)d_in[0];  // [32,1,64,64,100]
    const float* w   = (const float*)d_in[1];  // [8,1,6,6]
    const float* thr = (const float*)d_in[2];  // [1]
    float* out = (float*)d_out;                // [32,8,64,64,100]

    dim3 block(TILE_W, TILE_H, 1);             // 128 threads; all 8 couts per thread
    dim3 grid(NW / TILE_W, NH / TILE_H, NB);   // (4, 8, 32)
    sconv_spike_kernel<<<grid, block>>>(x, w, thr, out);
}

// round 9
// speedup vs baseline: 1.0683x; 1.0683x over previous
#include <cuda_runtime.h>

// Problem constants
#define NB    32
#define NH    64
#define NW    64
#define NT    100
#define COUT  8
#define KS    6
#define LP    2

// Tiling
#define TILE_W 16
#define TILE_H 8
#define HALO_W (TILE_W + KS - 1)   // 21
#define HALO_H (TILE_H + KS - 1)   // 13
#define NPIX   (HALO_W * HALO_H)   // 273
#define NTHR   256                 // 16 x 8 x 2 (cout split)
#define CPT    4                   // couts per thread
#define NCH    13                  // chunks 0..11: 8 timesteps, chunk 12: 4 (t=96..99)
#define NHWT   (NH * NW * NT)      // 409600
#define PSTRIDE 5                  // u64 per pixel in smem (40B stride -> conflict-free LDS.64)
#define NBUF   3                   // triple buffer, prefetch distance 2, 1 sync per chunk

typedef unsigned long long u64;

__device__ __forceinline__ void upk2(u64 v, float& lo, float& hi) {
    asm("mov.b64 {%0, %1}, %2;" : "=f"(lo), "=f"(hi) : "l"(v));
}
__device__ __forceinline__ u64 fma2(u64 a, u64 b, u64 c) {
    u64 d; asm("fma.rn.f32x2 %0, %1, %2, %3;" : "=l"(d) : "l"(a), "l"(b), "l"(c)); return d;
}
__device__ __forceinline__ unsigned smem_u32(const void* p) {
    return (unsigned)__cvta_generic_to_shared(p);
}
// 8-byte cp.async: only needs 8B alignment (PSTRIDE=5 pixel bases are 8B aligned)
__device__ __forceinline__ void cp8(unsigned dst, const void* src) {
    asm volatile("cp.async.ca.shared.global [%0], [%1], 8;" :: "r"(dst), "l"(src));
}
__device__ __forceinline__ void cp_commit() { asm volatile("cp.async.commit_group;" ::: "memory"); }
__device__ __forceinline__ void cp_wait1()  { asm volatile("cp.async.wait_group 1;" ::: "memory"); }
__device__ __forceinline__ void cp_wait0()  { asm volatile("cp.async.wait_group 0;" ::: "memory"); }

// exact reference recurrence step: ut = (ut - st_prev*thr) + wx ; st = (ut > 0)
__device__ __forceinline__ float stepf(float& u, float wx, float thr) {
    u = (u - (u > 0.f ? thr : 0.f)) + wx;
    return (u > 0.f) ? 1.f : 0.f;
}

__global__ __launch_bounds__(NTHR, 3)   // ~85 regs: slack for load hoisting; 24 warps/SM
void sconv_spike_kernel(const float* __restrict__ x,
                        const float* __restrict__ w,
                        const float* __restrict__ thr_p,
                        float* __restrict__ out)
{
    // triple-buffered input tile: pixel stride 5 u64 (40B) -> conflict-free LDS.64
    __shared__ u64 sx[NBUF][NPIX * PSTRIDE];
    // weights tap-major: sw2[tap*8 + cout], each duplicated (w,w) for f32x2
    __shared__ __align__(16) u64 sw2[KS * KS * COUT];

    const int tx  = threadIdx.x;
    const int ty  = threadIdx.y;
    const int cz  = threadIdx.z;          // cout half: couts [cz*4, cz*4+4)
    const int tid = tx + TILE_W * ty + (TILE_W * TILE_H) * cz;
    const int b   = blockIdx.z;
    const int h0  = blockIdx.y * TILE_H;
    const int w0  = blockIdx.x * TILE_W;

    // weights: transpose [cout][tap] -> [tap][cout], duplicate into both lanes
    for (int i = tid; i < KS * KS * COUT; i += NTHR) {
        int tap = i >> 3, c = i & 7;
        unsigned bits = __float_as_uint(w[c * (KS * KS) + tap]);
        sw2[i] = ((u64)bits << 32) | (u64)bits;
    }
    // zero OOB halo pixels in all buffers once (never written by cp8)
    for (int pix = tid; pix < NPIX; pix += NTHR) {
        int r = pix / HALO_W, c = pix % HALO_W;
        int gh = h0 - LP + r, gw = w0 - LP + c;
        if (gh < 0 || gh >= NH || gw < 0 || gw >= NW) {
#pragma unroll
            for (int bb = 0; bb < NBUF; bb++)
#pragma unroll
                for (int j = 0; j < 4; j++)
                    sx[bb][pix * PSTRIDE + j] = 0ull;
        }
    }
    const float thr = thr_p[0];

    const float* xb = x + (size_t)b * NH * NW * NT;
    const int h  = h0 + ty;
    const int wq = w0 + tx;
    const int cbase = cz * CPT;
    float* obase = out + (size_t)b * COUT * NHWT
                       + ((size_t)h * NW + wq) * NT
                       + (size_t)cbase * NHWT;

    float ut[CPT];
#pragma unroll
    for (int c = 0; c < CPT; c++) ut[c] = 0.f;

    // chunk loader: chunk k -> t0 = 8k; full chunks load 4 u64/pixel, tail loads 2
    auto load_chunk = [&](int k) {
        int buf = k % NBUF;
        int t0  = k * 8;
        int nu8 = (k == NCH - 1) ? 2 : 4;
        int total = NPIX * nu8;
        for (int idx = tid; idx < total; idx += NTHR) {
            int pix, j;
            if (nu8 == 4) { pix = idx >> 2; j = idx & 3; }
            else          { pix = idx >> 1; j = idx & 1; }
            int r = pix / HALO_W, c = pix % HALO_W;
            int gh = h0 - LP + r, gw = w0 - LP + c;
            if (gh >= 0 && gh < NH && gw >= 0 && gw < NW) {
                const float* src = xb + ((size_t)gh * NW + gw) * NT + t0 + j * 2;
                cp8(smem_u32(&sx[buf][pix * PSTRIDE + j]), src);
            }
        }
        cp_commit();
    };

    load_chunk(0);
    load_chunk(1);

#pragma unroll 1
    for (int i = 0; i < NCH; i++) {
        // outstanding cp.async groups at this point: {i, i+1}∩range
        if (i + 1 < NCH) cp_wait1();   // group i retired
        else             cp_wait0();
        __syncthreads();               // chunk i visible; iter i-1 reads done
        if (i + 2 < NCH) load_chunk(i + 2);   // safe: after the barrier

        const int buf = i % NBUF;
        const int t0  = i * 8;
        const bool full = (i != NCH - 1);

        u64 a0[CPT], a1[CPT], a2[CPT], a3[CPT];
#pragma unroll
        for (int c = 0; c < CPT; c++) { a0[c] = 0; a1[c] = 0; a2[c] = 0; a3[c] = 0; }

        if (full) {
            // software-pipelined tap loop: prefetch tap k+1's x during tap k's FFMAs
            const u64* xp = &sx[buf][(ty * HALO_W + tx) * PSTRIDE];  // tap 0 (kh=0,kw=0)
            u64 x0 = xp[0], x1 = xp[1], x2 = xp[2], x3 = xp[3];
#pragma unroll
            for (int tap = 0; tap < KS * KS; tap++) {
                u64 n0, n1, n2, n3;
                if (tap + 1 < KS * KS) {
                    const int nkh = (tap + 1) / KS, nkw = (tap + 1) % KS;
                    const u64* np = &sx[buf][((ty + nkh) * HALO_W + (tx + nkw)) * PSTRIDE];
                    n0 = np[0]; n1 = np[1]; n2 = np[2]; n3 = np[3];
                }
                ulonglong2 wA = *(const ulonglong2*)&sw2[tap * COUT + cbase];
                ulonglong2 wB = *(const ulonglong2*)&sw2[tap * COUT + cbase + 2];
                a0[0] = fma2(x0, wA.x, a0[0]); a1[0] = fma2(x1, wA.x, a1[0]);
                a2[0] = fma2(x2, wA.x, a2[0]); a3[0] = fma2(x3, wA.x, a3[0]);
                a0[1] = fma2(x0, wA.y, a0[1]); a1[1] = fma2(x1, wA.y, a1[1]);
                a2[1] = fma2(x2, wA.y, a2[1]); a3[1] = fma2(x3, wA.y, a3[1]);
                a0[2] = fma2(x0, wB.x, a0[2]); a1[2] = fma2(x1, wB.x, a1[2]);
                a2[2] = fma2(x2, wB.x, a2[2]); a3[2] = fma2(x3, wB.x, a3[2]);
                a0[3] = fma2(x0, wB.y, a0[3]); a1[3] = fma2(x1, wB.y, a1[3]);
                a2[3] = fma2(x2, wB.y, a2[3]); a3[3] = fma2(x3, wB.y, a3[3]);
                if (tap + 1 < KS * KS) { x0 = n0; x1 = n1; x2 = n2; x3 = n3; }
            }
#pragma unroll
            for (int c = 0; c < CPT; c++) {
                float wx0, wx1, wx2, wx3, wx4, wx5, wx6, wx7;
                upk2(a0[c], wx0, wx1); upk2(a1[c], wx2, wx3);
                upk2(a2[c], wx4, wx5); upk2(a3[c], wx6, wx7);
                float u = ut[c];
                float s0 = stepf(u, wx0, thr), s1 = stepf(u, wx1, thr);
                float s2 = stepf(u, wx2, thr), s3 = stepf(u, wx3, thr);
                float s4 = stepf(u, wx4, thr), s5 = stepf(u, wx5, thr);
                float s6 = stepf(u, wx6, thr), s7 = stepf(u, wx7, thr);
                ut[c] = u;
                float4* p = (float4*)(obase + (size_t)c * NHWT + t0);
                p[0] = make_float4(s0, s1, s2, s3);
                p[1] = make_float4(s4, s5, s6, s7);
            }
        } else {
            // tail: t = 96..99
#pragma unroll
            for (int kh = 0; kh < KS; kh++) {
#pragma unroll
                for (int kw = 0; kw < KS; kw++) {
                    const int tap = kh * KS + kw;
                    const u64* xp = &sx[buf][((ty + kh) * HALO_W + (tx + kw)) * PSTRIDE];
                    u64 x0 = xp[0], x1 = xp[1];
                    ulonglong2 wA = *(const ulonglong2*)&sw2[tap * COUT + cbase];
                    ulonglong2 wB = *(const ulonglong2*)&sw2[tap * COUT + cbase + 2];
                    a0[0] = fma2(x0, wA.x, a0[0]); a1[0] = fma2(x1, wA.x, a1[0]);
                    a0[1] = fma2(x0, wA.y, a0[1]); a1[1] = fma2(x1, wA.y, a1[1]);
                    a0[2] = fma2(x0, wB.x, a0[2]); a1[2] = fma2(x1, wB.x, a1[2]);
                    a0[3] = fma2(x0, wB.y, a0[3]); a1[3] = fma2(x1, wB.y, a1[3]);
                }
            }
#pragma unroll
            for (int c = 0; c < CPT; c++) {
                float wx0, wx1, wx2, wx3;
                upk2(a0[c], wx0, wx1); upk2(a1[c], wx2, wx3);
                float u = ut[c];
                float s0 = stepf(u, wx0, thr), s1 = stepf(u, wx1, thr);
                float s2 = stepf(u, wx2, thr), s3 = stepf(u, wx3, thr);
                ut[c] = u;
                *(float4*)(obase + (size_t)c * NHWT + t0) = make_float4(s0, s1, s2, s3);
            }
        }
    }
}

extern "C" void kernel_launch(void* const* d_in, const int* in_sizes, int n_in,
                              void* d_out, int out_size)
{
    const float* x   = (const float*)d_in[0];  // [32,1,64,64,100]
    const float* w   = (const float*)d_in[1];  // [8,1,6,6]
    const float* thr = (const float*)d_in[2];  // [1]
    float* out = (float*)d_out;                // [32,8,64,64,100]

    dim3 block(TILE_W, TILE_H, 2);             // 256 threads, cout split on z
    dim3 grid(NW / TILE_W, NH / TILE_H, NB);   // (4, 8, 32)
    sconv_spike_kernel<<<grid, block>>>(x, w, thr, out);
}